// round 13
// baseline (speedup 1.0000x reference)
#include <cuda_runtime.h>
#include <cuda_bf16.h>
#include <cstdint>

// ---------------------------------------------------------------------------
// Problem constants
// ---------------------------------------------------------------------------
#define B_       16
#define H_       56
#define W_       56
#define C_       768
#define WS_      14
#define NH_      12
#define HD_      64
#define NTOK_    196
#define NWIN_    256
#define M_ROWS   50176
#define K_DIM    768
#define N_QKV    2304
#define N_PROJ   768

// Scratch (device globals — allocation-free rule)
__device__ float g_qkv[(size_t)M_ROWS * N_QKV];
__device__ float g_o  [(size_t)M_ROWS * N_PROJ];
__device__ float g_xr [(size_t)M_ROWS * K_DIM];
__device__ float g_wq [(size_t)N_QKV  * K_DIM];
__device__ float g_wp [(size_t)N_PROJ * K_DIM];

// ---------------------------------------------------------------------------
// helpers
// ---------------------------------------------------------------------------
__device__ __forceinline__ float tf32_rna(float x) {
    uint32_t r;
    asm("cvt.rna.tf32.f32 %0, %1;" : "=r"(r) : "f"(x));
    return __uint_as_float(r);
}
__device__ __forceinline__ float4 rna4(float4 v) {
    v.x = tf32_rna(v.x); v.y = tf32_rna(v.y);
    v.z = tf32_rna(v.z); v.w = tf32_rna(v.w);
    return v;
}
__device__ __forceinline__ uint32_t smem_u32(const void* p) {
    uint32_t a;
    asm("{ .reg .u64 t; cvta.to.shared.u64 t, %1; cvt.u32.u64 %0, t; }" : "=r"(a) : "l"(p));
    return a;
}
__device__ __forceinline__ void cp_async16(uint32_t dst, const void* src) {
    asm volatile("cp.async.cg.shared.global [%0], [%1], 16;" :: "r"(dst), "l"(src) : "memory");
}
#define CP_COMMIT() asm volatile("cp.async.commit_group;" ::: "memory")
#define CP_WAIT(N)  asm volatile("cp.async.wait_group %0;" :: "n"(N) : "memory")

__device__ __forceinline__ void mma_m16n8k8(float d[4], const uint32_t a[4], const uint32_t b[2]) {
    asm volatile(
        "mma.sync.aligned.m16n8k8.row.col.f32.tf32.tf32.f32 "
        "{%0,%1,%2,%3}, {%4,%5,%6,%7}, {%8,%9}, {%0,%1,%2,%3};"
        : "+f"(d[0]), "+f"(d[1]), "+f"(d[2]), "+f"(d[3])
        : "r"(a[0]), "r"(a[1]), "r"(a[2]), "r"(a[3]), "r"(b[0]), "r"(b[1]));
}

// ---------------------------------------------------------------------------
// tf32 rounding kernel
// ---------------------------------------------------------------------------
__global__ void cvt_tf32_kernel(const float* __restrict__ in, float* __restrict__ out, int n4)
{
    int i = blockIdx.x * blockDim.x + threadIdx.x;
    if (i >= n4) return;
    ((float4*)out)[i] = rna4(((const float4*)in)[i]);
}

// ---------------------------------------------------------------------------
// tf32 mma.sync GEMM (NT): R6 config (best measured): 128x128x32 tile,
// 8 warps (warp tile 64x32), 2-stage cp.async, one sync/k-tile, 2 CTAs/SM,
// LDS.64 frag loads via k-slot re-pairing, ROWPAD=40 conflict-free.
// NEW: per-thread fragment base offsets hoisted out of the mainloop so every
// frag load is LDS [Rbase + imm] (kills inner-loop IMADs; alu% down).
// ---------------------------------------------------------------------------
#define BKG      32
#define STAGES   2
#define ROWPAD   40
#define TILE_B   (128 * ROWPAD * 4)            // 20480 B
#define TILE_W   (128 * ROWPAD)                // words per stage
#define GEMM_SMEM (2 * STAGES * TILE_B)        // 81920 B

__global__ __launch_bounds__(256, 2)
void gemm_tf32_mma(const float* __restrict__ A, const float* __restrict__ Bt,
                   const float* __restrict__ bias, float* __restrict__ C,
                   int M, int N, int K)
{
    extern __shared__ char sm[];
    float* smA = (float*)sm;
    float* smB = (float*)(sm + STAGES * TILE_B);

    const int tid  = threadIdx.x;
    const int wid  = tid >> 5;
    const int lane = tid & 31;
    const int g    = lane >> 2;
    const int t    = lane & 3;
    const int m0   = blockIdx.y * 128;
    const int n0   = blockIdx.x * 128;
    const int wm   = (wid & 1) * 64;
    const int wn   = (wid >> 1) * 32;
    const int ktiles = K / BKG;

    const uint32_t sbA = smem_u32(smA);
    const uint32_t sbB = smem_u32(smB);

    // hoisted per-thread fragment bases (per stage)
    const int aoff = (wm + g) * ROWPAD + 2 * t;
    const int boff = (wn + g) * ROWPAD + 2 * t;
    const float* Aw[2] = { smA + aoff, smA + TILE_W + aoff };
    const float* Bw[2] = { smB + boff, smB + TILE_W + boff };

    auto issue_tile = [&](int kt, int s) {
        const float* Ag = A  + (size_t)m0 * K + (size_t)kt * BKG;
        const float* Bg = Bt + (size_t)n0 * K + (size_t)kt * BKG;
        #pragma unroll
        for (int i = 0; i < 4; i++) {
            const int f   = tid + 256 * i;
            const int row = f >> 3;
            const int c4  = f & 7;
            const uint32_t so = (uint32_t)(s * TILE_B + (row * ROWPAD + c4 * 4) * 4);
            cp_async16(sbA + so, Ag + (size_t)row * K + c4 * 4);
            cp_async16(sbB + so, Bg + (size_t)row * K + c4 * 4);
        }
    };

    issue_tile(0, 0); CP_COMMIT();

    float acc[4][4][4];
    #pragma unroll
    for (int i = 0; i < 4; i++)
        #pragma unroll
        for (int j = 0; j < 4; j++)
            #pragma unroll
            for (int r = 0; r < 4; r++) acc[i][j][r] = 0.f;

    for (int kt = 0; kt < ktiles; kt++) {
        CP_WAIT(0);
        __syncthreads();
        if (kt + 1 < ktiles) {
            issue_tile(kt + 1, (kt + 1) & 1);
            CP_COMMIT();
        }

        const int s = kt & 1;
        const float* Ap = Aw[s];
        const float* Bp = Bw[s];

        #pragma unroll
        for (int kk = 0; kk < 4; kk++) {
            uint32_t a[4][4];
            #pragma unroll
            for (int fm = 0; fm < 4; fm++) {
                const float2 lo = *(const float2*)&Ap[fm * 16 * ROWPAD + kk * 8];
                const float2 hi = *(const float2*)&Ap[(fm * 16 + 8) * ROWPAD + kk * 8];
                a[fm][0] = __float_as_uint(lo.x);
                a[fm][1] = __float_as_uint(hi.x);
                a[fm][2] = __float_as_uint(lo.y);
                a[fm][3] = __float_as_uint(hi.y);
            }
            uint32_t b[4][2];
            #pragma unroll
            for (int fn = 0; fn < 4; fn++) {
                const float2 v = *(const float2*)&Bp[fn * 8 * ROWPAD + kk * 8];
                b[fn][0] = __float_as_uint(v.x);
                b[fn][1] = __float_as_uint(v.y);
            }
            #pragma unroll
            for (int fm = 0; fm < 4; fm++)
                #pragma unroll
                for (int fn = 0; fn < 4; fn++)
                    mma_m16n8k8(acc[fm][fn], a[fm], b[fn]);
        }
    }
    __syncthreads();

    #pragma unroll
    for (int fm = 0; fm < 4; fm++) {
        const int r0 = m0 + wm + fm * 16 + g;
        #pragma unroll
        for (int fn = 0; fn < 4; fn++) {
            const int c = n0 + wn + fn * 8 + 2 * t;
            const float b0 = bias[c], b1 = bias[c + 1];
            float2 v0 = make_float2(acc[fm][fn][0] + b0, acc[fm][fn][1] + b1);
            float2 v1 = make_float2(acc[fm][fn][2] + b0, acc[fm][fn][3] + b1);
            *(float2*)(C + (size_t)r0 * N + c)       = v0;
            *(float2*)(C + (size_t)(r0 + 8) * N + c) = v1;
        }
    }
}

// ---------------------------------------------------------------------------
// Tensor-core fused window attention — the Round-7 measured-best version:
// 256 threads (8 warps), online softmax, P through warp-private smem,
// tail chunk of 8 keys, warp 7 early-exit after the fill barrier.
// ---------------------------------------------------------------------------
#define KPAD 68
#define VPAD 72
#define PPAD 68
#define AT_SMEM ((256 * KPAD + 256 * VPAD + 8 * 32 * PPAD) * 4)   // 212992 B

__global__ __launch_bounds__(256, 1)
void win_attn_tc(const float* __restrict__ qkv, float* __restrict__ o)
{
    extern __shared__ float s[];
    float* Ks = s;
    float* Vs = Ks + 256 * KPAD;
    float* Ps = Vs + 256 * VPAD;

    const int head = blockIdx.x;
    const int win  = blockIdx.y;
    const int b  = win >> 4;
    const int hb = (win >> 2) & 3;
    const int wb = win & 3;

    const int tid  = threadIdx.x;
    const int w    = tid >> 5;
    const int lane = tid & 31;
    const int g    = lane >> 2;
    const int t    = lane & 3;

    for (int idx = tid; idx < 200 * 16; idx += 256) {
        const int n  = idx >> 4;
        const int d4 = (idx & 15) * 4;
        float4 kv = make_float4(0.f, 0.f, 0.f, 0.f);
        float4 vv = kv;
        if (n < NTOK_) {
            const int rr = n / WS_;
            const int cc = n - rr * WS_;
            const size_t row = (size_t)((b * H_ + hb * WS_ + rr) * W_ + (wb * WS_ + cc));
            const float* p = qkv + row * N_QKV + head * HD_ + d4;
            kv = rna4(*(const float4*)(p + C_));
            vv = rna4(*(const float4*)(p + 2 * C_));
        }
        *(float4*)&Ks[n * KPAD + d4] = kv;
        *(float4*)&Vs[n * VPAD + d4] = vv;
    }

    int rb[2][2];
    #pragma unroll
    for (int mt = 0; mt < 2; mt++)
        #pragma unroll
        for (int hf = 0; hf < 2; hf++) {
            const int n = w * 32 + mt * 16 + g + hf * 8;
            if (n < NTOK_) {
                const int rr = n / WS_;
                const int cc = n - rr * WS_;
                rb[mt][hf] = (b * H_ + hb * WS_ + rr) * W_ + (wb * WS_ + cc);
            } else rb[mt][hf] = -1;
        }

    uint32_t q[2][8][4];
    #pragma unroll
    for (int mt = 0; mt < 2; mt++) {
        const float* p0 = (rb[mt][0] >= 0) ? qkv + (size_t)rb[mt][0] * N_QKV + head * HD_ : nullptr;
        const float* p1 = (rb[mt][1] >= 0) ? qkv + (size_t)rb[mt][1] * N_QKV + head * HD_ : nullptr;
        #pragma unroll
        for (int kk = 0; kk < 8; kk++) {
            float v0 = p0 ? p0[kk * 8 + t]     : 0.f;
            float v2 = p0 ? p0[kk * 8 + t + 4] : 0.f;
            float v1 = p1 ? p1[kk * 8 + t]     : 0.f;
            float v3 = p1 ? p1[kk * 8 + t + 4] : 0.f;
            q[mt][kk][0] = __float_as_uint(tf32_rna(v0 * 0.125f));
            q[mt][kk][1] = __float_as_uint(tf32_rna(v1 * 0.125f));
            q[mt][kk][2] = __float_as_uint(tf32_rna(v2 * 0.125f));
            q[mt][kk][3] = __float_as_uint(tf32_rna(v3 * 0.125f));
        }
    }
    __syncthreads();

    if (w == 7) return;                     // rows 224..255 all padding

    float oacc[2][8][4];
    #pragma unroll
    for (int mt = 0; mt < 2; mt++)
        #pragma unroll
        for (int nt = 0; nt < 8; nt++)
            #pragma unroll
            for (int r = 0; r < 4; r++) oacc[mt][nt][r] = 0.f;

    float mrow[2][2] = {{-1e30f, -1e30f}, {-1e30f, -1e30f}};
    float lrow[2][2] = {{0.f, 0.f}, {0.f, 0.f}};
    float* Pw = Ps + w * 32 * PPAD;

    for (int c = 0; c < 3; c++) {
        const int n0c = c * 64;

        float sacc[2][8][4];
        #pragma unroll
        for (int mt = 0; mt < 2; mt++)
            #pragma unroll
            for (int nt = 0; nt < 8; nt++)
                #pragma unroll
                for (int r = 0; r < 4; r++) sacc[mt][nt][r] = 0.f;

        #pragma unroll
        for (int kk = 0; kk < 8; kk++) {
            #pragma unroll
            for (int nt = 0; nt < 8; nt++) {
                const float* kp = Ks + (n0c + nt * 8 + g) * KPAD + kk * 8 + t;
                uint32_t bfr[2];
                bfr[0] = __float_as_uint(kp[0]);
                bfr[1] = __float_as_uint(kp[4]);
                mma_m16n8k8(sacc[0][nt], q[0][kk], bfr);
                mma_m16n8k8(sacc[1][nt], q[1][kk], bfr);
            }
        }

        #pragma unroll
        for (int mt = 0; mt < 2; mt++) {
            float mx0 = -1e30f, mx1 = -1e30f;
            #pragma unroll
            for (int nt = 0; nt < 8; nt++) {
                mx0 = fmaxf(mx0, fmaxf(sacc[mt][nt][0], sacc[mt][nt][1]));
                mx1 = fmaxf(mx1, fmaxf(sacc[mt][nt][2], sacc[mt][nt][3]));
            }
            mx0 = fmaxf(mx0, __shfl_xor_sync(0xffffffffu, mx0, 1));
            mx0 = fmaxf(mx0, __shfl_xor_sync(0xffffffffu, mx0, 2));
            mx1 = fmaxf(mx1, __shfl_xor_sync(0xffffffffu, mx1, 1));
            mx1 = fmaxf(mx1, __shfl_xor_sync(0xffffffffu, mx1, 2));

            const float mn0 = fmaxf(mrow[mt][0], mx0);
            const float mn1 = fmaxf(mrow[mt][1], mx1);
            const float al0 = __expf(mrow[mt][0] - mn0);
            const float al1 = __expf(mrow[mt][1] - mn1);
            mrow[mt][0] = mn0; mrow[mt][1] = mn1;

            float s0 = 0.f, s1 = 0.f;
            float* pr0 = Pw + (mt * 16 + g) * PPAD;
            float* pr1 = pr0 + 8 * PPAD;
            #pragma unroll
            for (int nt = 0; nt < 8; nt++) {
                const float p0 = __expf(sacc[mt][nt][0] - mn0);
                const float p1 = __expf(sacc[mt][nt][1] - mn0);
                const float p2 = __expf(sacc[mt][nt][2] - mn1);
                const float p3 = __expf(sacc[mt][nt][3] - mn1);
                s0 += p0 + p1;
                s1 += p2 + p3;
                *(float2*)&pr0[nt * 8 + 2 * t] = make_float2(tf32_rna(p0), tf32_rna(p1));
                *(float2*)&pr1[nt * 8 + 2 * t] = make_float2(tf32_rna(p2), tf32_rna(p3));
            }
            s0 += __shfl_xor_sync(0xffffffffu, s0, 1);
            s0 += __shfl_xor_sync(0xffffffffu, s0, 2);
            s1 += __shfl_xor_sync(0xffffffffu, s1, 1);
            s1 += __shfl_xor_sync(0xffffffffu, s1, 2);
            lrow[mt][0] = lrow[mt][0] * al0 + s0;
            lrow[mt][1] = lrow[mt][1] * al1 + s1;

            #pragma unroll
            for (int nt = 0; nt < 8; nt++) {
                oacc[mt][nt][0] *= al0; oacc[mt][nt][1] *= al0;
                oacc[mt][nt][2] *= al1; oacc[mt][nt][3] *= al1;
            }
        }
        __syncwarp();

        #pragma unroll
        for (int kk2 = 0; kk2 < 8; kk2++) {
            uint32_t a[2][4];
            #pragma unroll
            for (int mt = 0; mt < 2; mt++) {
                const float* pp = Pw + (mt * 16 + g) * PPAD + kk2 * 8 + t;
                a[mt][0] = __float_as_uint(pp[0]);
                a[mt][1] = __float_as_uint(pp[8 * PPAD]);
                a[mt][2] = __float_as_uint(pp[4]);
                a[mt][3] = __float_as_uint(pp[8 * PPAD + 4]);
            }
            #pragma unroll
            for (int ntd = 0; ntd < 8; ntd++) {
                const float* vp = Vs + (n0c + kk2 * 8 + t) * VPAD + ntd * 8 + g;
                uint32_t bfr[2];
                bfr[0] = __float_as_uint(vp[0]);
                bfr[1] = __float_as_uint(vp[4 * VPAD]);
                mma_m16n8k8(oacc[0][ntd], a[0], bfr);
                mma_m16n8k8(oacc[1][ntd], a[1], bfr);
            }
        }
        __syncwarp();
    }

    // ---- tail chunk: keys 192..199 (one n-tile, 4 valid keys) ----
    {
        float st[2][4] = {{0.f, 0.f, 0.f, 0.f}, {0.f, 0.f, 0.f, 0.f}};
        #pragma unroll
        for (int kk = 0; kk < 8; kk++) {
            const float* kp = Ks + (192 + g) * KPAD + kk * 8 + t;
            uint32_t bfr[2];
            bfr[0] = __float_as_uint(kp[0]);
            bfr[1] = __float_as_uint(kp[4]);
            mma_m16n8k8(st[0], q[0][kk], bfr);
            mma_m16n8k8(st[1], q[1][kk], bfr);
        }
        const int j0 = 192 + 2 * t;
        #pragma unroll
        for (int mt = 0; mt < 2; mt++) {
            if (j0 >= NTOK_)     { st[mt][0] = -1e30f; st[mt][2] = -1e30f; }
            if (j0 + 1 >= NTOK_) { st[mt][1] = -1e30f; st[mt][3] = -1e30f; }

            float mx0 = fmaxf(st[mt][0], st[mt][1]);
            float mx1 = fmaxf(st[mt][2], st[mt][3]);
            mx0 = fmaxf(mx0, __shfl_xor_sync(0xffffffffu, mx0, 1));
            mx0 = fmaxf(mx0, __shfl_xor_sync(0xffffffffu, mx0, 2));
            mx1 = fmaxf(mx1, __shfl_xor_sync(0xffffffffu, mx1, 1));
            mx1 = fmaxf(mx1, __shfl_xor_sync(0xffffffffu, mx1, 2));

            const float mn0 = fmaxf(mrow[mt][0], mx0);
            const float mn1 = fmaxf(mrow[mt][1], mx1);
            const float al0 = __expf(mrow[mt][0] - mn0);
            const float al1 = __expf(mrow[mt][1] - mn1);
            mrow[mt][0] = mn0; mrow[mt][1] = mn1;

            const float p0 = __expf(st[mt][0] - mn0);
            const float p1 = __expf(st[mt][1] - mn0);
            const float p2 = __expf(st[mt][2] - mn1);
            const float p3 = __expf(st[mt][3] - mn1);
            float s0 = p0 + p1, s1 = p2 + p3;
            float* pr0 = Pw + (mt * 16 + g) * PPAD;
            float* pr1 = pr0 + 8 * PPAD;
            *(float2*)&pr0[2 * t] = make_float2(tf32_rna(p0), tf32_rna(p1));
            *(float2*)&pr1[2 * t] = make_float2(tf32_rna(p2), tf32_rna(p3));

            s0 += __shfl_xor_sync(0xffffffffu, s0, 1);
            s0 += __shfl_xor_sync(0xffffffffu, s0, 2);
            s1 += __shfl_xor_sync(0xffffffffu, s1, 1);
            s1 += __shfl_xor_sync(0xffffffffu, s1, 2);
            lrow[mt][0] = lrow[mt][0] * al0 + s0;
            lrow[mt][1] = lrow[mt][1] * al1 + s1;

            #pragma unroll
            for (int nt = 0; nt < 8; nt++) {
                oacc[mt][nt][0] *= al0; oacc[mt][nt][1] *= al0;
                oacc[mt][nt][2] *= al1; oacc[mt][nt][3] *= al1;
            }
        }
        __syncwarp();

        uint32_t a[2][4];
        #pragma unroll
        for (int mt = 0; mt < 2; mt++) {
            const float* pp = Pw + (mt * 16 + g) * PPAD + t;
            a[mt][0] = __float_as_uint(pp[0]);
            a[mt][1] = __float_as_uint(pp[8 * PPAD]);
            a[mt][2] = __float_as_uint(pp[4]);
            a[mt][3] = __float_as_uint(pp[8 * PPAD + 4]);
        }
        #pragma unroll
        for (int ntd = 0; ntd < 8; ntd++) {
            const float* vp = Vs + (192 + t) * VPAD + ntd * 8 + g;
            uint32_t bfr[2];
            bfr[0] = __float_as_uint(vp[0]);
            bfr[1] = __float_as_uint(vp[4 * VPAD]);
            mma_m16n8k8(oacc[0][ntd], a[0], bfr);
            mma_m16n8k8(oacc[1][ntd], a[1], bfr);
        }
    }

    // ---- epilogue ----
    #pragma unroll
    for (int mt = 0; mt < 2; mt++) {
        const float i0 = 1.f / lrow[mt][0];
        const float i1 = 1.f / lrow[mt][1];
        if (rb[mt][0] >= 0) {
            float* op = o + (size_t)rb[mt][0] * N_PROJ + head * HD_;
            #pragma unroll
            for (int ntd = 0; ntd < 8; ntd++)
                *(float2*)&op[ntd * 8 + 2 * t] =
                    make_float2(tf32_rna(oacc[mt][ntd][0] * i0), tf32_rna(oacc[mt][ntd][1] * i0));
        }
        if (rb[mt][1] >= 0) {
            float* op = o + (size_t)rb[mt][1] * N_PROJ + head * HD_;
            #pragma unroll
            for (int ntd = 0; ntd < 8; ntd++)
                *(float2*)&op[ntd * 8 + 2 * t] =
                    make_float2(tf32_rna(oacc[mt][ntd][2] * i1), tf32_rna(oacc[mt][ntd][3] * i1));
        }
    }
}

// ---------------------------------------------------------------------------
extern "C" void kernel_launch(void* const* d_in, const int* in_sizes, int n_in,
                              void* d_out, int out_size)
{
    const float* x      = (const float*)d_in[0];
    const float* qkv_w  = (const float*)d_in[1];
    const float* qkv_b  = (const float*)d_in[2];
    const float* proj_w = (const float*)d_in[3];
    const float* proj_b = (const float*)d_in[4];
    float* out = (float*)d_out;

    float *qkv_s, *o_s, *xr, *wq, *wp;
    cudaGetSymbolAddress((void**)&qkv_s, g_qkv);
    cudaGetSymbolAddress((void**)&o_s,   g_o);
    cudaGetSymbolAddress((void**)&xr,    g_xr);
    cudaGetSymbolAddress((void**)&wq,    g_wq);
    cudaGetSymbolAddress((void**)&wp,    g_wp);

    cudaFuncSetAttribute(gemm_tf32_mma,
                         cudaFuncAttributeMaxDynamicSharedMemorySize, GEMM_SMEM);
    cudaFuncSetAttribute(win_attn_tc,
                         cudaFuncAttributeMaxDynamicSharedMemorySize, AT_SMEM);

    // 0) tf32-round GEMM inputs (rna)
    {
        int n4 = M_ROWS * K_DIM / 4;
        cvt_tf32_kernel<<<(n4 + 255) / 256, 256>>>(x, xr, n4);
        n4 = N_QKV * K_DIM / 4;
        cvt_tf32_kernel<<<(n4 + 255) / 256, 256>>>(qkv_w, wq, n4);
        n4 = N_PROJ * K_DIM / 4;
        cvt_tf32_kernel<<<(n4 + 255) / 256, 256>>>(proj_w, wp, n4);
    }

    // 1) QKV GEMM
    {
        dim3 grid(N_QKV / 128, M_ROWS / 128);
        gemm_tf32_mma<<<grid, 256, GEMM_SMEM>>>(xr, wq, qkv_b, qkv_s,
                                                M_ROWS, N_QKV, K_DIM);
    }

    // 2) fused tensor-core window attention
    {
        dim3 grid(NH_, NWIN_);
        win_attn_tc<<<grid, 256, AT_SMEM>>>(qkv_s, o_s);
    }

    // 3) proj GEMM -> final output
    {
        dim3 grid(N_PROJ / 128, M_ROWS / 128);
        gemm_tf32_mma<<<grid, 256, GEMM_SMEM>>>(o_s, wp, proj_b, out,
                                                M_ROWS, N_PROJ, K_DIM);
    }
}

// round 15
// speedup vs baseline: 1.1060x; 1.1060x over previous
#include <cuda_runtime.h>
#include <cuda_bf16.h>
#include <cstdint>

// ---------------------------------------------------------------------------
// Problem constants
// ---------------------------------------------------------------------------
#define B_       16
#define H_       56
#define W_       56
#define C_       768
#define WS_      14
#define NH_      12
#define HD_      64
#define NTOK_    196
#define NWIN_    256
#define M_ROWS   50176
#define K_DIM    768
#define N_QKV    2304
#define N_PROJ   768

// Scratch (device globals — allocation-free rule)
__device__ float g_qkv[(size_t)M_ROWS * N_QKV];
__device__ float g_o  [(size_t)M_ROWS * N_PROJ];
__device__ float g_xr [(size_t)M_ROWS * K_DIM];
__device__ float g_wq [(size_t)N_QKV  * K_DIM];
__device__ float g_wp [(size_t)N_PROJ * K_DIM];

// ---------------------------------------------------------------------------
// helpers
// ---------------------------------------------------------------------------
__device__ __forceinline__ float tf32_rna(float x) {
    uint32_t r;
    asm("cvt.rna.tf32.f32 %0, %1;" : "=r"(r) : "f"(x));
    return __uint_as_float(r);
}
__device__ __forceinline__ float4 rna4(float4 v) {
    v.x = tf32_rna(v.x); v.y = tf32_rna(v.y);
    v.z = tf32_rna(v.z); v.w = tf32_rna(v.w);
    return v;
}
__device__ __forceinline__ uint32_t smem_u32(const void* p) {
    uint32_t a;
    asm("{ .reg .u64 t; cvta.to.shared.u64 t, %1; cvt.u32.u64 %0, t; }" : "=r"(a) : "l"(p));
    return a;
}
__device__ __forceinline__ void cp_async16(uint32_t dst, const void* src) {
    asm volatile("cp.async.cg.shared.global [%0], [%1], 16;" :: "r"(dst), "l"(src) : "memory");
}
#define CP_COMMIT() asm volatile("cp.async.commit_group;" ::: "memory")
#define CP_WAIT(N)  asm volatile("cp.async.wait_group %0;" :: "n"(N) : "memory")

__device__ __forceinline__ void mma_m16n8k8(float d[4], const uint32_t a[4], const uint32_t b[2]) {
    asm volatile(
        "mma.sync.aligned.m16n8k8.row.col.f32.tf32.tf32.f32 "
        "{%0,%1,%2,%3}, {%4,%5,%6,%7}, {%8,%9}, {%0,%1,%2,%3};"
        : "+f"(d[0]), "+f"(d[1]), "+f"(d[2]), "+f"(d[3])
        : "r"(a[0]), "r"(a[1]), "r"(a[2]), "r"(a[3]), "r"(b[0]), "r"(b[1]));
}

// ---------------------------------------------------------------------------
// tf32 rounding kernel
// ---------------------------------------------------------------------------
__global__ void cvt_tf32_kernel(const float* __restrict__ in, float* __restrict__ out, int n4)
{
    int i = blockIdx.x * blockDim.x + threadIdx.x;
    if (i >= n4) return;
    ((float4*)out)[i] = rna4(((const float4*)in)[i]);
}

// ---------------------------------------------------------------------------
// tf32 mma.sync GEMM (NT) — EXACT R6 text (measured best 921-926us QKV,
// 4 independent runs): 128x128x32 tile, 8 warps (warp tile 64x32), 2-stage
// cp.async, one __syncthreads per k-tile, 2 CTAs/SM, LDS.64 fragment loads
// via k-slot re-pairing (cols 2t,2t+1), ROWPAD=40 bank-conflict-free.
// Do NOT touch this mainloop without SASS evidence (R13 lesson).
// ---------------------------------------------------------------------------
#define BKG      32
#define STAGES   2
#define ROWPAD   40
#define TILE_B   (128 * ROWPAD * 4)            // 20480 B
#define GEMM_SMEM (2 * STAGES * TILE_B)        // 81920 B

__global__ __launch_bounds__(256, 2)
void gemm_tf32_mma(const float* __restrict__ A, const float* __restrict__ Bt,
                   const float* __restrict__ bias, float* __restrict__ C,
                   int M, int N, int K)
{
    extern __shared__ char sm[];
    float* smA = (float*)sm;
    float* smB = (float*)(sm + STAGES * TILE_B);

    const int tid  = threadIdx.x;
    const int wid  = tid >> 5;
    const int lane = tid & 31;
    const int g    = lane >> 2;
    const int t    = lane & 3;
    const int m0   = blockIdx.y * 128;
    const int n0   = blockIdx.x * 128;
    const int wm   = (wid & 1) * 64;
    const int wn   = (wid >> 1) * 32;
    const int ktiles = K / BKG;

    const uint32_t sbA = smem_u32(smA);
    const uint32_t sbB = smem_u32(smB);

    auto issue_tile = [&](int kt, int s) {
        const float* Ag = A  + (size_t)m0 * K + (size_t)kt * BKG;
        const float* Bg = Bt + (size_t)n0 * K + (size_t)kt * BKG;
        #pragma unroll
        for (int i = 0; i < 4; i++) {
            const int f   = tid + 256 * i;
            const int row = f >> 3;
            const int c4  = f & 7;
            const uint32_t so = (uint32_t)(s * TILE_B + (row * ROWPAD + c4 * 4) * 4);
            cp_async16(sbA + so, Ag + (size_t)row * K + c4 * 4);
            cp_async16(sbB + so, Bg + (size_t)row * K + c4 * 4);
        }
    };

    issue_tile(0, 0); CP_COMMIT();

    float acc[4][4][4];
    #pragma unroll
    for (int i = 0; i < 4; i++)
        #pragma unroll
        for (int j = 0; j < 4; j++)
            #pragma unroll
            for (int r = 0; r < 4; r++) acc[i][j][r] = 0.f;

    for (int kt = 0; kt < ktiles; kt++) {
        CP_WAIT(0);
        __syncthreads();
        if (kt + 1 < ktiles) {
            issue_tile(kt + 1, (kt + 1) & 1);
            CP_COMMIT();
        }

        const int s = kt & 1;
        const float* As = smA + s * (TILE_B / 4);
        const float* Bs = smB + s * (TILE_B / 4);

        #pragma unroll
        for (int kk = 0; kk < 4; kk++) {
            uint32_t a[4][4];
            #pragma unroll
            for (int fm = 0; fm < 4; fm++) {
                const int ra = wm + fm * 16 + g;
                const float2 lo = *(const float2*)&As[ra * ROWPAD + kk * 8 + 2 * t];
                const float2 hi = *(const float2*)&As[(ra + 8) * ROWPAD + kk * 8 + 2 * t];
                a[fm][0] = __float_as_uint(lo.x);
                a[fm][1] = __float_as_uint(hi.x);
                a[fm][2] = __float_as_uint(lo.y);
                a[fm][3] = __float_as_uint(hi.y);
            }
            uint32_t b[4][2];
            #pragma unroll
            for (int fn = 0; fn < 4; fn++) {
                const float2 v = *(const float2*)&Bs[(wn + fn * 8 + g) * ROWPAD + kk * 8 + 2 * t];
                b[fn][0] = __float_as_uint(v.x);
                b[fn][1] = __float_as_uint(v.y);
            }
            #pragma unroll
            for (int fm = 0; fm < 4; fm++)
                #pragma unroll
                for (int fn = 0; fn < 4; fn++)
                    mma_m16n8k8(acc[fm][fn], a[fm], b[fn]);
        }
    }
    __syncthreads();

    #pragma unroll
    for (int fm = 0; fm < 4; fm++) {
        const int r0 = m0 + wm + fm * 16 + g;
        #pragma unroll
        for (int fn = 0; fn < 4; fn++) {
            const int c = n0 + wn + fn * 8 + 2 * t;
            const float b0 = bias[c], b1 = bias[c + 1];
            float2 v0 = make_float2(acc[fm][fn][0] + b0, acc[fm][fn][1] + b1);
            float2 v1 = make_float2(acc[fm][fn][2] + b0, acc[fm][fn][3] + b1);
            *(float2*)(C + (size_t)r0 * N + c)       = v0;
            *(float2*)(C + (size_t)(r0 + 8) * N + c) = v1;
        }
    }
}

// ---------------------------------------------------------------------------
// Tensor-core fused window attention — EXACT R7 text (measured best):
// 256 threads (8 warps), online softmax, P through warp-private smem,
// tail chunk of 8 keys, warp 7 early-exit after the fill barrier.
// ---------------------------------------------------------------------------
#define KPAD 68
#define VPAD 72
#define PPAD 68
#define AT_SMEM ((256 * KPAD + 256 * VPAD + 8 * 32 * PPAD) * 4)   // 212992 B

__global__ __launch_bounds__(256, 1)
void win_attn_tc(const float* __restrict__ qkv, float* __restrict__ o)
{
    extern __shared__ float s[];
    float* Ks = s;
    float* Vs = Ks + 256 * KPAD;
    float* Ps = Vs + 256 * VPAD;

    const int head = blockIdx.x;
    const int win  = blockIdx.y;
    const int b  = win >> 4;
    const int hb = (win >> 2) & 3;
    const int wb = win & 3;

    const int tid  = threadIdx.x;
    const int w    = tid >> 5;
    const int lane = tid & 31;
    const int g    = lane >> 2;
    const int t    = lane & 3;

    for (int idx = tid; idx < 200 * 16; idx += 256) {
        const int n  = idx >> 4;
        const int d4 = (idx & 15) * 4;
        float4 kv = make_float4(0.f, 0.f, 0.f, 0.f);
        float4 vv = kv;
        if (n < NTOK_) {
            const int rr = n / WS_;
            const int cc = n - rr * WS_;
            const size_t row = (size_t)((b * H_ + hb * WS_ + rr) * W_ + (wb * WS_ + cc));
            const float* p = qkv + row * N_QKV + head * HD_ + d4;
            kv = rna4(*(const float4*)(p + C_));
            vv = rna4(*(const float4*)(p + 2 * C_));
        }
        *(float4*)&Ks[n * KPAD + d4] = kv;
        *(float4*)&Vs[n * VPAD + d4] = vv;
    }

    int rb[2][2];
    #pragma unroll
    for (int mt = 0; mt < 2; mt++)
        #pragma unroll
        for (int hf = 0; hf < 2; hf++) {
            const int n = w * 32 + mt * 16 + g + hf * 8;
            if (n < NTOK_) {
                const int rr = n / WS_;
                const int cc = n - rr * WS_;
                rb[mt][hf] = (b * H_ + hb * WS_ + rr) * W_ + (wb * WS_ + cc);
            } else rb[mt][hf] = -1;
        }

    uint32_t q[2][8][4];
    #pragma unroll
    for (int mt = 0; mt < 2; mt++) {
        const float* p0 = (rb[mt][0] >= 0) ? qkv + (size_t)rb[mt][0] * N_QKV + head * HD_ : nullptr;
        const float* p1 = (rb[mt][1] >= 0) ? qkv + (size_t)rb[mt][1] * N_QKV + head * HD_ : nullptr;
        #pragma unroll
        for (int kk = 0; kk < 8; kk++) {
            float v0 = p0 ? p0[kk * 8 + t]     : 0.f;
            float v2 = p0 ? p0[kk * 8 + t + 4] : 0.f;
            float v1 = p1 ? p1[kk * 8 + t]     : 0.f;
            float v3 = p1 ? p1[kk * 8 + t + 4] : 0.f;
            q[mt][kk][0] = __float_as_uint(tf32_rna(v0 * 0.125f));
            q[mt][kk][1] = __float_as_uint(tf32_rna(v1 * 0.125f));
            q[mt][kk][2] = __float_as_uint(tf32_rna(v2 * 0.125f));
            q[mt][kk][3] = __float_as_uint(tf32_rna(v3 * 0.125f));
        }
    }
    __syncthreads();

    if (w == 7) return;                     // rows 224..255 all padding

    float oacc[2][8][4];
    #pragma unroll
    for (int mt = 0; mt < 2; mt++)
        #pragma unroll
        for (int nt = 0; nt < 8; nt++)
            #pragma unroll
            for (int r = 0; r < 4; r++) oacc[mt][nt][r] = 0.f;

    float mrow[2][2] = {{-1e30f, -1e30f}, {-1e30f, -1e30f}};
    float lrow[2][2] = {{0.f, 0.f}, {0.f, 0.f}};
    float* Pw = Ps + w * 32 * PPAD;

    for (int c = 0; c < 3; c++) {
        const int n0c = c * 64;

        float sacc[2][8][4];
        #pragma unroll
        for (int mt = 0; mt < 2; mt++)
            #pragma unroll
            for (int nt = 0; nt < 8; nt++)
                #pragma unroll
                for (int r = 0; r < 4; r++) sacc[mt][nt][r] = 0.f;

        #pragma unroll
        for (int kk = 0; kk < 8; kk++) {
            #pragma unroll
            for (int nt = 0; nt < 8; nt++) {
                const float* kp = Ks + (n0c + nt * 8 + g) * KPAD + kk * 8 + t;
                uint32_t bfr[2];
                bfr[0] = __float_as_uint(kp[0]);
                bfr[1] = __float_as_uint(kp[4]);
                mma_m16n8k8(sacc[0][nt], q[0][kk], bfr);
                mma_m16n8k8(sacc[1][nt], q[1][kk], bfr);
            }
        }

        #pragma unroll
        for (int mt = 0; mt < 2; mt++) {
            float mx0 = -1e30f, mx1 = -1e30f;
            #pragma unroll
            for (int nt = 0; nt < 8; nt++) {
                mx0 = fmaxf(mx0, fmaxf(sacc[mt][nt][0], sacc[mt][nt][1]));
                mx1 = fmaxf(mx1, fmaxf(sacc[mt][nt][2], sacc[mt][nt][3]));
            }
            mx0 = fmaxf(mx0, __shfl_xor_sync(0xffffffffu, mx0, 1));
            mx0 = fmaxf(mx0, __shfl_xor_sync(0xffffffffu, mx0, 2));
            mx1 = fmaxf(mx1, __shfl_xor_sync(0xffffffffu, mx1, 1));
            mx1 = fmaxf(mx1, __shfl_xor_sync(0xffffffffu, mx1, 2));

            const float mn0 = fmaxf(mrow[mt][0], mx0);
            const float mn1 = fmaxf(mrow[mt][1], mx1);
            const float al0 = __expf(mrow[mt][0] - mn0);
            const float al1 = __expf(mrow[mt][1] - mn1);
            mrow[mt][0] = mn0; mrow[mt][1] = mn1;

            float s0 = 0.f, s1 = 0.f;
            float* pr0 = Pw + (mt * 16 + g) * PPAD;
            float* pr1 = pr0 + 8 * PPAD;
            #pragma unroll
            for (int nt = 0; nt < 8; nt++) {
                const float p0 = __expf(sacc[mt][nt][0] - mn0);
                const float p1 = __expf(sacc[mt][nt][1] - mn0);
                const float p2 = __expf(sacc[mt][nt][2] - mn1);
                const float p3 = __expf(sacc[mt][nt][3] - mn1);
                s0 += p0 + p1;
                s1 += p2 + p3;
                *(float2*)&pr0[nt * 8 + 2 * t] = make_float2(tf32_rna(p0), tf32_rna(p1));
                *(float2*)&pr1[nt * 8 + 2 * t] = make_float2(tf32_rna(p2), tf32_rna(p3));
            }
            s0 += __shfl_xor_sync(0xffffffffu, s0, 1);
            s0 += __shfl_xor_sync(0xffffffffu, s0, 2);
            s1 += __shfl_xor_sync(0xffffffffu, s1, 1);
            s1 += __shfl_xor_sync(0xffffffffu, s1, 2);
            lrow[mt][0] = lrow[mt][0] * al0 + s0;
            lrow[mt][1] = lrow[mt][1] * al1 + s1;

            #pragma unroll
            for (int nt = 0; nt < 8; nt++) {
                oacc[mt][nt][0] *= al0; oacc[mt][nt][1] *= al0;
                oacc[mt][nt][2] *= al1; oacc[mt][nt][3] *= al1;
            }
        }
        __syncwarp();

        #pragma unroll
        for (int kk2 = 0; kk2 < 8; kk2++) {
            uint32_t a[2][4];
            #pragma unroll
            for (int mt = 0; mt < 2; mt++) {
                const float* pp = Pw + (mt * 16 + g) * PPAD + kk2 * 8 + t;
                a[mt][0] = __float_as_uint(pp[0]);
                a[mt][1] = __float_as_uint(pp[8 * PPAD]);
                a[mt][2] = __float_as_uint(pp[4]);
                a[mt][3] = __float_as_uint(pp[8 * PPAD + 4]);
            }
            #pragma unroll
            for (int ntd = 0; ntd < 8; ntd++) {
                const float* vp = Vs + (n0c + kk2 * 8 + t) * VPAD + ntd * 8 + g;
                uint32_t bfr[2];
                bfr[0] = __float_as_uint(vp[0]);
                bfr[1] = __float_as_uint(vp[4 * VPAD]);
                mma_m16n8k8(oacc[0][ntd], a[0], bfr);
                mma_m16n8k8(oacc[1][ntd], a[1], bfr);
            }
        }
        __syncwarp();
    }

    // ---- tail chunk: keys 192..199 (one n-tile, 4 valid keys) ----
    {
        float st[2][4] = {{0.f, 0.f, 0.f, 0.f}, {0.f, 0.f, 0.f, 0.f}};
        #pragma unroll
        for (int kk = 0; kk < 8; kk++) {
            const float* kp = Ks + (192 + g) * KPAD + kk * 8 + t;
            uint32_t bfr[2];
            bfr[0] = __float_as_uint(kp[0]);
            bfr[1] = __float_as_uint(kp[4]);
            mma_m16n8k8(st[0], q[0][kk], bfr);
            mma_m16n8k8(st[1], q[1][kk], bfr);
        }
        const int j0 = 192 + 2 * t;
        #pragma unroll
        for (int mt = 0; mt < 2; mt++) {
            if (j0 >= NTOK_)     { st[mt][0] = -1e30f; st[mt][2] = -1e30f; }
            if (j0 + 1 >= NTOK_) { st[mt][1] = -1e30f; st[mt][3] = -1e30f; }

            float mx0 = fmaxf(st[mt][0], st[mt][1]);
            float mx1 = fmaxf(st[mt][2], st[mt][3]);
            mx0 = fmaxf(mx0, __shfl_xor_sync(0xffffffffu, mx0, 1));
            mx0 = fmaxf(mx0, __shfl_xor_sync(0xffffffffu, mx0, 2));
            mx1 = fmaxf(mx1, __shfl_xor_sync(0xffffffffu, mx1, 1));
            mx1 = fmaxf(mx1, __shfl_xor_sync(0xffffffffu, mx1, 2));

            const float mn0 = fmaxf(mrow[mt][0], mx0);
            const float mn1 = fmaxf(mrow[mt][1], mx1);
            const float al0 = __expf(mrow[mt][0] - mn0);
            const float al1 = __expf(mrow[mt][1] - mn1);
            mrow[mt][0] = mn0; mrow[mt][1] = mn1;

            const float p0 = __expf(st[mt][0] - mn0);
            const float p1 = __expf(st[mt][1] - mn0);
            const float p2 = __expf(st[mt][2] - mn1);
            const float p3 = __expf(st[mt][3] - mn1);
            float s0 = p0 + p1, s1 = p2 + p3;
            float* pr0 = Pw + (mt * 16 + g) * PPAD;
            float* pr1 = pr0 + 8 * PPAD;
            *(float2*)&pr0[2 * t] = make_float2(tf32_rna(p0), tf32_rna(p1));
            *(float2*)&pr1[2 * t] = make_float2(tf32_rna(p2), tf32_rna(p3));

            s0 += __shfl_xor_sync(0xffffffffu, s0, 1);
            s0 += __shfl_xor_sync(0xffffffffu, s0, 2);
            s1 += __shfl_xor_sync(0xffffffffu, s1, 1);
            s1 += __shfl_xor_sync(0xffffffffu, s1, 2);
            lrow[mt][0] = lrow[mt][0] * al0 + s0;
            lrow[mt][1] = lrow[mt][1] * al1 + s1;

            #pragma unroll
            for (int nt = 0; nt < 8; nt++) {
                oacc[mt][nt][0] *= al0; oacc[mt][nt][1] *= al0;
                oacc[mt][nt][2] *= al1; oacc[mt][nt][3] *= al1;
            }
        }
        __syncwarp();

        uint32_t a[2][4];
        #pragma unroll
        for (int mt = 0; mt < 2; mt++) {
            const float* pp = Pw + (mt * 16 + g) * PPAD + t;
            a[mt][0] = __float_as_uint(pp[0]);
            a[mt][1] = __float_as_uint(pp[8 * PPAD]);
            a[mt][2] = __float_as_uint(pp[4]);
            a[mt][3] = __float_as_uint(pp[8 * PPAD + 4]);
        }
        #pragma unroll
        for (int ntd = 0; ntd < 8; ntd++) {
            const float* vp = Vs + (192 + t) * VPAD + ntd * 8 + g;
            uint32_t bfr[2];
            bfr[0] = __float_as_uint(vp[0]);
            bfr[1] = __float_as_uint(vp[4 * VPAD]);
            mma_m16n8k8(oacc[0][ntd], a[0], bfr);
            mma_m16n8k8(oacc[1][ntd], a[1], bfr);
        }
    }

    // ---- epilogue ----
    #pragma unroll
    for (int mt = 0; mt < 2; mt++) {
        const float i0 = 1.f / lrow[mt][0];
        const float i1 = 1.f / lrow[mt][1];
        if (rb[mt][0] >= 0) {
            float* op = o + (size_t)rb[mt][0] * N_PROJ + head * HD_;
            #pragma unroll
            for (int ntd = 0; ntd < 8; ntd++)
                *(float2*)&op[ntd * 8 + 2 * t] =
                    make_float2(tf32_rna(oacc[mt][ntd][0] * i0), tf32_rna(oacc[mt][ntd][1] * i0));
        }
        if (rb[mt][1] >= 0) {
            float* op = o + (size_t)rb[mt][1] * N_PROJ + head * HD_;
            #pragma unroll
            for (int ntd = 0; ntd < 8; ntd++)
                *(float2*)&op[ntd * 8 + 2 * t] =
                    make_float2(tf32_rna(oacc[mt][ntd][2] * i1), tf32_rna(oacc[mt][ntd][3] * i1));
        }
    }
}

// ---------------------------------------------------------------------------
extern "C" void kernel_launch(void* const* d_in, const int* in_sizes, int n_in,
                              void* d_out, int out_size)
{
    const float* x      = (const float*)d_in[0];
    const float* qkv_w  = (const float*)d_in[1];
    const float* qkv_b  = (const float*)d_in[2];
    const float* proj_w = (const float*)d_in[3];
    const float* proj_b = (const float*)d_in[4];
    float* out = (float*)d_out;

    float *qkv_s, *o_s, *xr, *wq, *wp;
    cudaGetSymbolAddress((void**)&qkv_s, g_qkv);
    cudaGetSymbolAddress((void**)&o_s,   g_o);
    cudaGetSymbolAddress((void**)&xr,    g_xr);
    cudaGetSymbolAddress((void**)&wq,    g_wq);
    cudaGetSymbolAddress((void**)&wp,    g_wp);

    cudaFuncSetAttribute(gemm_tf32_mma,
                         cudaFuncAttributeMaxDynamicSharedMemorySize, GEMM_SMEM);
    cudaFuncSetAttribute(win_attn_tc,
                         cudaFuncAttributeMaxDynamicSharedMemorySize, AT_SMEM);

    // 0) tf32-round GEMM inputs (rna)
    {
        int n4 = M_ROWS * K_DIM / 4;
        cvt_tf32_kernel<<<(n4 + 255) / 256, 256>>>(x, xr, n4);
        n4 = N_QKV * K_DIM / 4;
        cvt_tf32_kernel<<<(n4 + 255) / 256, 256>>>(qkv_w, wq, n4);
        n4 = N_PROJ * K_DIM / 4;
        cvt_tf32_kernel<<<(n4 + 255) / 256, 256>>>(proj_w, wp, n4);
    }

    // 1) QKV GEMM
    {
        dim3 grid(N_QKV / 128, M_ROWS / 128);
        gemm_tf32_mma<<<grid, 256, GEMM_SMEM>>>(xr, wq, qkv_b, qkv_s,
                                                M_ROWS, N_QKV, K_DIM);
    }

    // 2) fused tensor-core window attention
    {
        dim3 grid(NH_, NWIN_);
        win_attn_tc<<<grid, 256, AT_SMEM>>>(qkv_s, o_s);
    }

    // 3) proj GEMM -> final output
    {
        dim3 grid(N_PROJ / 128, M_ROWS / 128);
        gemm_tf32_mma<<<grid, 256, GEMM_SMEM>>>(o_s, wp, proj_b, out,
                                                M_ROWS, N_PROJ, K_DIM);
    }
}

// round 16
// speedup vs baseline: 1.1423x; 1.0329x over previous
#include <cuda_runtime.h>
#include <cuda_bf16.h>
#include <cstdint>

// ---------------------------------------------------------------------------
// Problem constants
// ---------------------------------------------------------------------------
#define B_       16
#define H_       56
#define W_       56
#define C_       768
#define WS_      14
#define NH_      12
#define HD_      64
#define NTOK_    196
#define NWIN_    256
#define M_ROWS   50176
#define K_DIM    768
#define N_QKV    2304
#define N_PROJ   768

// Scratch (device globals — allocation-free rule)
__device__ float g_qkv[(size_t)M_ROWS * N_QKV];
__device__ float g_o  [(size_t)M_ROWS * N_PROJ];
__device__ float g_xr [(size_t)M_ROWS * K_DIM];
__device__ float g_wq [(size_t)N_QKV  * K_DIM];
__device__ float g_wp [(size_t)N_PROJ * K_DIM];

// ---------------------------------------------------------------------------
// helpers
// ---------------------------------------------------------------------------
__device__ __forceinline__ float tf32_rna(float x) {
    uint32_t r;
    asm("cvt.rna.tf32.f32 %0, %1;" : "=r"(r) : "f"(x));
    return __uint_as_float(r);
}
__device__ __forceinline__ float4 rna4(float4 v) {
    v.x = tf32_rna(v.x); v.y = tf32_rna(v.y);
    v.z = tf32_rna(v.z); v.w = tf32_rna(v.w);
    return v;
}
__device__ __forceinline__ uint32_t smem_u32(const void* p) {
    uint32_t a;
    asm("{ .reg .u64 t; cvta.to.shared.u64 t, %1; cvt.u32.u64 %0, t; }" : "=r"(a) : "l"(p));
    return a;
}
__device__ __forceinline__ void cp_async16(uint32_t dst, const void* src) {
    asm volatile("cp.async.cg.shared.global [%0], [%1], 16;" :: "r"(dst), "l"(src) : "memory");
}
#define CP_COMMIT() asm volatile("cp.async.commit_group;" ::: "memory")
#define CP_WAIT(N)  asm volatile("cp.async.wait_group %0;" :: "n"(N) : "memory")

__device__ __forceinline__ void mma_m16n8k8(float d[4], const uint32_t a[4], const uint32_t b[2]) {
    asm volatile(
        "mma.sync.aligned.m16n8k8.row.col.f32.tf32.tf32.f32 "
        "{%0,%1,%2,%3}, {%4,%5,%6,%7}, {%8,%9}, {%0,%1,%2,%3};"
        : "+f"(d[0]), "+f"(d[1]), "+f"(d[2]), "+f"(d[3])
        : "r"(a[0]), "r"(a[1]), "r"(a[2]), "r"(a[3]), "r"(b[0]), "r"(b[1]));
}

// ---------------------------------------------------------------------------
// Merged tf32 rounding kernel: x, qkv_w, proj_w in ONE launch.
// ---------------------------------------------------------------------------
#define NX4 (M_ROWS * K_DIM / 4)
#define NQ4 (N_QKV  * K_DIM / 4)
#define NP4 (N_PROJ * K_DIM / 4)

__global__ void cvt_all_kernel(const float* __restrict__ x,  float* __restrict__ xr,
                               const float* __restrict__ wqi, float* __restrict__ wq,
                               const float* __restrict__ wpi, float* __restrict__ wp)
{
    int i = blockIdx.x * blockDim.x + threadIdx.x;
    if (i < NX4) { ((float4*)xr)[i] = rna4(((const float4*)x)[i]); return; }
    i -= NX4;
    if (i < NQ4) { ((float4*)wq)[i] = rna4(((const float4*)wqi)[i]); return; }
    i -= NQ4;
    if (i < NP4) ((float4*)wp)[i] = rna4(((const float4*)wpi)[i]);
}

// ---------------------------------------------------------------------------
// tf32 mma.sync GEMM (NT) — EXACT R6 text (measured best, 4 runs at 921-926us
// QKV): 128x128x32 tile, 8 warps (warp tile 64x32), 2-stage cp.async, one
// __syncthreads per k-tile, 2 CTAs/SM, LDS.64 frag loads via k-slot
// re-pairing (cols 2t,2t+1), ROWPAD=40 bank-conflict-free. DO NOT TOUCH.
// ---------------------------------------------------------------------------
#define BKG      32
#define STAGES   2
#define ROWPAD   40
#define TILE_B   (128 * ROWPAD * 4)            // 20480 B
#define GEMM_SMEM (2 * STAGES * TILE_B)        // 81920 B

__global__ __launch_bounds__(256, 2)
void gemm_tf32_mma(const float* __restrict__ A, const float* __restrict__ Bt,
                   const float* __restrict__ bias, float* __restrict__ C,
                   int M, int N, int K)
{
    extern __shared__ char sm[];
    float* smA = (float*)sm;
    float* smB = (float*)(sm + STAGES * TILE_B);

    const int tid  = threadIdx.x;
    const int wid  = tid >> 5;
    const int lane = tid & 31;
    const int g    = lane >> 2;
    const int t    = lane & 3;
    const int m0   = blockIdx.y * 128;
    const int n0   = blockIdx.x * 128;
    const int wm   = (wid & 1) * 64;
    const int wn   = (wid >> 1) * 32;
    const int ktiles = K / BKG;

    const uint32_t sbA = smem_u32(smA);
    const uint32_t sbB = smem_u32(smB);

    auto issue_tile = [&](int kt, int s) {
        const float* Ag = A  + (size_t)m0 * K + (size_t)kt * BKG;
        const float* Bg = Bt + (size_t)n0 * K + (size_t)kt * BKG;
        #pragma unroll
        for (int i = 0; i < 4; i++) {
            const int f   = tid + 256 * i;
            const int row = f >> 3;
            const int c4  = f & 7;
            const uint32_t so = (uint32_t)(s * TILE_B + (row * ROWPAD + c4 * 4) * 4);
            cp_async16(sbA + so, Ag + (size_t)row * K + c4 * 4);
            cp_async16(sbB + so, Bg + (size_t)row * K + c4 * 4);
        }
    };

    issue_tile(0, 0); CP_COMMIT();

    float acc[4][4][4];
    #pragma unroll
    for (int i = 0; i < 4; i++)
        #pragma unroll
        for (int j = 0; j < 4; j++)
            #pragma unroll
            for (int r = 0; r < 4; r++) acc[i][j][r] = 0.f;

    for (int kt = 0; kt < ktiles; kt++) {
        CP_WAIT(0);
        __syncthreads();
        if (kt + 1 < ktiles) {
            issue_tile(kt + 1, (kt + 1) & 1);
            CP_COMMIT();
        }

        const int s = kt & 1;
        const float* As = smA + s * (TILE_B / 4);
        const float* Bs = smB + s * (TILE_B / 4);

        #pragma unroll
        for (int kk = 0; kk < 4; kk++) {
            uint32_t a[4][4];
            #pragma unroll
            for (int fm = 0; fm < 4; fm++) {
                const int ra = wm + fm * 16 + g;
                const float2 lo = *(const float2*)&As[ra * ROWPAD + kk * 8 + 2 * t];
                const float2 hi = *(const float2*)&As[(ra + 8) * ROWPAD + kk * 8 + 2 * t];
                a[fm][0] = __float_as_uint(lo.x);
                a[fm][1] = __float_as_uint(hi.x);
                a[fm][2] = __float_as_uint(lo.y);
                a[fm][3] = __float_as_uint(hi.y);
            }
            uint32_t b[4][2];
            #pragma unroll
            for (int fn = 0; fn < 4; fn++) {
                const float2 v = *(const float2*)&Bs[(wn + fn * 8 + g) * ROWPAD + kk * 8 + 2 * t];
                b[fn][0] = __float_as_uint(v.x);
                b[fn][1] = __float_as_uint(v.y);
            }
            #pragma unroll
            for (int fm = 0; fm < 4; fm++)
                #pragma unroll
                for (int fn = 0; fn < 4; fn++)
                    mma_m16n8k8(acc[fm][fn], a[fm], b[fn]);
        }
    }
    __syncthreads();

    #pragma unroll
    for (int fm = 0; fm < 4; fm++) {
        const int r0 = m0 + wm + fm * 16 + g;
        #pragma unroll
        for (int fn = 0; fn < 4; fn++) {
            const int c = n0 + wn + fn * 8 + 2 * t;
            const float b0 = bias[c], b1 = bias[c + 1];
            float2 v0 = make_float2(acc[fm][fn][0] + b0, acc[fm][fn][1] + b1);
            float2 v1 = make_float2(acc[fm][fn][2] + b0, acc[fm][fn][3] + b1);
            *(float2*)(C + (size_t)r0 * N + c)       = v0;
            *(float2*)(C + (size_t)(r0 + 8) * N + c) = v1;
        }
    }
}

// ---------------------------------------------------------------------------
// Tensor-core fused window attention — R7 packaging + register-resident P:
// 256 threads (8 warps), ONE K/V fill per (win,head), warp-7 exit,
// online softmax writing rounded p back into sacc (R11 arithmetic),
// PV a-frags straight from registers (k-slot pairing: a-slots = keys 2t,2t+1),
// K b-frag = one LDS.64 (KPAD=72 conflict-free),
// V b-frag = two LDS.32 at rows 2t,2t+1 (VPAD=68 conflict-free).
// No P smem, no __syncwarp in the mainloop. smem 112 KB.
// ---------------------------------------------------------------------------
#define KPAD 72
#define VPAD 68
#define AT_SMEM ((200 * KPAD + 200 * VPAD) * 4)   // 112000 B

__global__ __launch_bounds__(256, 1)
void win_attn_tc(const float* __restrict__ qkv, float* __restrict__ o)
{
    extern __shared__ float s[];
    float* Ks = s;                 // [200][KPAD]
    float* Vs = Ks + 200 * KPAD;   // [200][VPAD]

    const int head = blockIdx.x;
    const int win  = blockIdx.y;
    const int b  = win >> 4;
    const int hb = (win >> 2) & 3;
    const int wb = win & 3;

    const int tid  = threadIdx.x;
    const int w    = tid >> 5;
    const int lane = tid & 31;
    const int g    = lane >> 2;
    const int t    = lane & 3;

    // ---- K/V fill (rows 0..199; 196..199 zero), tf32-rounded ----
    for (int idx = tid; idx < 200 * 16; idx += 256) {
        const int n  = idx >> 4;
        const int d4 = (idx & 15) * 4;
        float4 kv = make_float4(0.f, 0.f, 0.f, 0.f);
        float4 vv = kv;
        if (n < NTOK_) {
            const int rr = n / WS_;
            const int cc = n - rr * WS_;
            const size_t row = (size_t)((b * H_ + hb * WS_ + rr) * W_ + (wb * WS_ + cc));
            const float* p = qkv + row * N_QKV + head * HD_ + d4;
            kv = rna4(*(const float4*)(p + C_));
            vv = rna4(*(const float4*)(p + 2 * C_));
        }
        *(float4*)&Ks[n * KPAD + d4] = kv;
        *(float4*)&Vs[n * VPAD + d4] = vv;
    }

    // ---- raster bases for this thread's 4 query rows ----
    int rb[2][2];
    #pragma unroll
    for (int mt = 0; mt < 2; mt++)
        #pragma unroll
        for (int hf = 0; hf < 2; hf++) {
            const int n = w * 32 + mt * 16 + g + hf * 8;
            if (n < NTOK_) {
                const int rr = n / WS_;
                const int cc = n - rr * WS_;
                rb[mt][hf] = (b * H_ + hb * WS_ + rr) * W_ + (wb * WS_ + cc);
            } else rb[mt][hf] = -1;
        }

    // ---- Q a-frags (slots = cols 2t,2t+1; pre-scaled, tf32-rounded) ----
    uint32_t q[2][8][4];
    #pragma unroll
    for (int mt = 0; mt < 2; mt++) {
        const float* p0 = (rb[mt][0] >= 0) ? qkv + (size_t)rb[mt][0] * N_QKV + head * HD_ : nullptr;
        const float* p1 = (rb[mt][1] >= 0) ? qkv + (size_t)rb[mt][1] * N_QKV + head * HD_ : nullptr;
        #pragma unroll
        for (int kk = 0; kk < 8; kk++) {
            float2 lo = p0 ? *(const float2*)(p0 + kk * 8 + 2 * t) : make_float2(0.f, 0.f);
            float2 hi = p1 ? *(const float2*)(p1 + kk * 8 + 2 * t) : make_float2(0.f, 0.f);
            q[mt][kk][0] = __float_as_uint(tf32_rna(lo.x * 0.125f));
            q[mt][kk][1] = __float_as_uint(tf32_rna(hi.x * 0.125f));
            q[mt][kk][2] = __float_as_uint(tf32_rna(lo.y * 0.125f));
            q[mt][kk][3] = __float_as_uint(tf32_rna(hi.y * 0.125f));
        }
    }
    __syncthreads();

    if (w == 7) return;                     // rows 224..255 all padding

    float oacc[2][8][4];
    #pragma unroll
    for (int mt = 0; mt < 2; mt++)
        #pragma unroll
        for (int nt = 0; nt < 8; nt++)
            #pragma unroll
            for (int r = 0; r < 4; r++) oacc[mt][nt][r] = 0.f;

    float mrow[2][2] = {{-1e30f, -1e30f}, {-1e30f, -1e30f}};
    float lrow[2][2] = {{0.f, 0.f}, {0.f, 0.f}};

    // ---- 3 full chunks of 64 keys ----
    for (int c = 0; c < 3; c++) {
        const int n0c = c * 64;

        float sacc[2][8][4];
        #pragma unroll
        for (int mt = 0; mt < 2; mt++)
            #pragma unroll
            for (int nt = 0; nt < 8; nt++)
                #pragma unroll
                for (int r = 0; r < 4; r++) sacc[mt][nt][r] = 0.f;

        #pragma unroll
        for (int kk = 0; kk < 8; kk++) {
            #pragma unroll
            for (int nt = 0; nt < 8; nt++) {
                const float2 kv = *(const float2*)&Ks[(n0c + nt * 8 + g) * KPAD + kk * 8 + 2 * t];
                uint32_t bfr[2];
                bfr[0] = __float_as_uint(kv.x);
                bfr[1] = __float_as_uint(kv.y);
                mma_m16n8k8(sacc[0][nt], q[0][kk], bfr);
                mma_m16n8k8(sacc[1][nt], q[1][kk], bfr);
            }
        }

        // online softmax; rounded p overwrites sacc (PV a-frag source)
        #pragma unroll
        for (int mt = 0; mt < 2; mt++) {
            float mx0 = -1e30f, mx1 = -1e30f;
            #pragma unroll
            for (int nt = 0; nt < 8; nt++) {
                mx0 = fmaxf(mx0, fmaxf(sacc[mt][nt][0], sacc[mt][nt][1]));
                mx1 = fmaxf(mx1, fmaxf(sacc[mt][nt][2], sacc[mt][nt][3]));
            }
            mx0 = fmaxf(mx0, __shfl_xor_sync(0xffffffffu, mx0, 1));
            mx0 = fmaxf(mx0, __shfl_xor_sync(0xffffffffu, mx0, 2));
            mx1 = fmaxf(mx1, __shfl_xor_sync(0xffffffffu, mx1, 1));
            mx1 = fmaxf(mx1, __shfl_xor_sync(0xffffffffu, mx1, 2));

            const float mn0 = fmaxf(mrow[mt][0], mx0);
            const float mn1 = fmaxf(mrow[mt][1], mx1);
            const float al0 = __expf(mrow[mt][0] - mn0);
            const float al1 = __expf(mrow[mt][1] - mn1);
            mrow[mt][0] = mn0; mrow[mt][1] = mn1;

            float s0 = 0.f, s1 = 0.f;
            #pragma unroll
            for (int nt = 0; nt < 8; nt++) {
                const float p0 = __expf(sacc[mt][nt][0] - mn0);
                const float p1 = __expf(sacc[mt][nt][1] - mn0);
                const float p2 = __expf(sacc[mt][nt][2] - mn1);
                const float p3 = __expf(sacc[mt][nt][3] - mn1);
                s0 += p0 + p1;
                s1 += p2 + p3;
                sacc[mt][nt][0] = tf32_rna(p0);
                sacc[mt][nt][1] = tf32_rna(p1);
                sacc[mt][nt][2] = tf32_rna(p2);
                sacc[mt][nt][3] = tf32_rna(p3);
            }
            s0 += __shfl_xor_sync(0xffffffffu, s0, 1);
            s0 += __shfl_xor_sync(0xffffffffu, s0, 2);
            s1 += __shfl_xor_sync(0xffffffffu, s1, 1);
            s1 += __shfl_xor_sync(0xffffffffu, s1, 2);
            lrow[mt][0] = lrow[mt][0] * al0 + s0;
            lrow[mt][1] = lrow[mt][1] * al1 + s1;

            #pragma unroll
            for (int nt = 0; nt < 8; nt++) {
                oacc[mt][nt][0] *= al0; oacc[mt][nt][1] *= al0;
                oacc[mt][nt][2] *= al1; oacc[mt][nt][3] *= al1;
            }
        }

        // PV: a-frag = register P (slots = keys 2t,2t+1), b = V rows (2t,2t+1)
        #pragma unroll
        for (int kk2 = 0; kk2 < 8; kk2++) {
            uint32_t a0[4], a1[4];
            a0[0] = __float_as_uint(sacc[0][kk2][0]);
            a0[1] = __float_as_uint(sacc[0][kk2][2]);
            a0[2] = __float_as_uint(sacc[0][kk2][1]);
            a0[3] = __float_as_uint(sacc[0][kk2][3]);
            a1[0] = __float_as_uint(sacc[1][kk2][0]);
            a1[1] = __float_as_uint(sacc[1][kk2][2]);
            a1[2] = __float_as_uint(sacc[1][kk2][1]);
            a1[3] = __float_as_uint(sacc[1][kk2][3]);
            const float* v0p = Vs + (n0c + kk2 * 8 + 2 * t) * VPAD;
            #pragma unroll
            for (int ntd = 0; ntd < 8; ntd++) {
                uint32_t bfr[2];
                bfr[0] = __float_as_uint(v0p[ntd * 8 + g]);
                bfr[1] = __float_as_uint(v0p[VPAD + ntd * 8 + g]);
                mma_m16n8k8(oacc[0][ntd], a0, bfr);
                mma_m16n8k8(oacc[1][ntd], a1, bfr);
            }
        }
    }

    // ---- tail chunk: keys 192..199 (4 valid) ----
    {
        float st[2][4] = {{0.f, 0.f, 0.f, 0.f}, {0.f, 0.f, 0.f, 0.f}};
        #pragma unroll
        for (int kk = 0; kk < 8; kk++) {
            const float2 kv = *(const float2*)&Ks[(192 + g) * KPAD + kk * 8 + 2 * t];
            uint32_t bfr[2];
            bfr[0] = __float_as_uint(kv.x);
            bfr[1] = __float_as_uint(kv.y);
            mma_m16n8k8(st[0], q[0][kk], bfr);
            mma_m16n8k8(st[1], q[1][kk], bfr);
        }
        const int j0 = 192 + 2 * t;
        #pragma unroll
        for (int mt = 0; mt < 2; mt++) {
            if (j0 >= NTOK_)     { st[mt][0] = -1e30f; st[mt][2] = -1e30f; }
            if (j0 + 1 >= NTOK_) { st[mt][1] = -1e30f; st[mt][3] = -1e30f; }

            float mx0 = fmaxf(st[mt][0], st[mt][1]);
            float mx1 = fmaxf(st[mt][2], st[mt][3]);
            mx0 = fmaxf(mx0, __shfl_xor_sync(0xffffffffu, mx0, 1));
            mx0 = fmaxf(mx0, __shfl_xor_sync(0xffffffffu, mx0, 2));
            mx1 = fmaxf(mx1, __shfl_xor_sync(0xffffffffu, mx1, 1));
            mx1 = fmaxf(mx1, __shfl_xor_sync(0xffffffffu, mx1, 2));

            const float mn0 = fmaxf(mrow[mt][0], mx0);
            const float mn1 = fmaxf(mrow[mt][1], mx1);
            const float al0 = __expf(mrow[mt][0] - mn0);
            const float al1 = __expf(mrow[mt][1] - mn1);
            mrow[mt][0] = mn0; mrow[mt][1] = mn1;

            const float p0 = __expf(st[mt][0] - mn0);
            const float p1 = __expf(st[mt][1] - mn0);
            const float p2 = __expf(st[mt][2] - mn1);
            const float p3 = __expf(st[mt][3] - mn1);
            float s0 = p0 + p1, s1 = p2 + p3;
            st[mt][0] = tf32_rna(p0);
            st[mt][1] = tf32_rna(p1);
            st[mt][2] = tf32_rna(p2);
            st[mt][3] = tf32_rna(p3);

            s0 += __shfl_xor_sync(0xffffffffu, s0, 1);
            s0 += __shfl_xor_sync(0xffffffffu, s0, 2);
            s1 += __shfl_xor_sync(0xffffffffu, s1, 1);
            s1 += __shfl_xor_sync(0xffffffffu, s1, 2);
            lrow[mt][0] = lrow[mt][0] * al0 + s0;
            lrow[mt][1] = lrow[mt][1] * al1 + s1;

            #pragma unroll
            for (int nt = 0; nt < 8; nt++) {
                oacc[mt][nt][0] *= al0; oacc[mt][nt][1] *= al0;
                oacc[mt][nt][2] *= al1; oacc[mt][nt][3] *= al1;
            }
        }

        uint32_t a0[4], a1[4];
        a0[0] = __float_as_uint(st[0][0]);
        a0[1] = __float_as_uint(st[0][2]);
        a0[2] = __float_as_uint(st[0][1]);
        a0[3] = __float_as_uint(st[0][3]);
        a1[0] = __float_as_uint(st[1][0]);
        a1[1] = __float_as_uint(st[1][2]);
        a1[2] = __float_as_uint(st[1][1]);
        a1[3] = __float_as_uint(st[1][3]);
        const float* v0p = Vs + (192 + 2 * t) * VPAD;
        #pragma unroll
        for (int ntd = 0; ntd < 8; ntd++) {
            uint32_t bfr[2];
            bfr[0] = __float_as_uint(v0p[ntd * 8 + g]);
            bfr[1] = __float_as_uint(v0p[VPAD + ntd * 8 + g]);
            mma_m16n8k8(oacc[0][ntd], a0, bfr);
            mma_m16n8k8(oacc[1][ntd], a1, bfr);
        }
    }

    // ---- epilogue ----
    #pragma unroll
    for (int mt = 0; mt < 2; mt++) {
        const float i0 = 1.f / lrow[mt][0];
        const float i1 = 1.f / lrow[mt][1];
        if (rb[mt][0] >= 0) {
            float* op = o + (size_t)rb[mt][0] * N_PROJ + head * HD_;
            #pragma unroll
            for (int ntd = 0; ntd < 8; ntd++)
                *(float2*)&op[ntd * 8 + 2 * t] =
                    make_float2(tf32_rna(oacc[mt][ntd][0] * i0), tf32_rna(oacc[mt][ntd][1] * i0));
        }
        if (rb[mt][1] >= 0) {
            float* op = o + (size_t)rb[mt][1] * N_PROJ + head * HD_;
            #pragma unroll
            for (int ntd = 0; ntd < 8; ntd++)
                *(float2*)&op[ntd * 8 + 2 * t] =
                    make_float2(tf32_rna(oacc[mt][ntd][2] * i1), tf32_rna(oacc[mt][ntd][3] * i1));
        }
    }
}

// ---------------------------------------------------------------------------
extern "C" void kernel_launch(void* const* d_in, const int* in_sizes, int n_in,
                              void* d_out, int out_size)
{
    const float* x      = (const float*)d_in[0];
    const float* qkv_w  = (const float*)d_in[1];
    const float* qkv_b  = (const float*)d_in[2];
    const float* proj_w = (const float*)d_in[3];
    const float* proj_b = (const float*)d_in[4];
    float* out = (float*)d_out;

    float *qkv_s, *o_s, *xr, *wq, *wp;
    cudaGetSymbolAddress((void**)&qkv_s, g_qkv);
    cudaGetSymbolAddress((void**)&o_s,   g_o);
    cudaGetSymbolAddress((void**)&xr,    g_xr);
    cudaGetSymbolAddress((void**)&wq,    g_wq);
    cudaGetSymbolAddress((void**)&wp,    g_wp);

    cudaFuncSetAttribute(gemm_tf32_mma,
                         cudaFuncAttributeMaxDynamicSharedMemorySize, GEMM_SMEM);
    cudaFuncSetAttribute(win_attn_tc,
                         cudaFuncAttributeMaxDynamicSharedMemorySize, AT_SMEM);

    // 0) tf32-round all GEMM inputs in ONE launch
    {
        const int ntot = NX4 + NQ4 + NP4;
        cvt_all_kernel<<<(ntot + 255) / 256, 256>>>(x, xr, qkv_w, wq, proj_w, wp);
    }

    // 1) QKV GEMM
    {
        dim3 grid(N_QKV / 128, M_ROWS / 128);
        gemm_tf32_mma<<<grid, 256, GEMM_SMEM>>>(xr, wq, qkv_b, qkv_s,
                                                M_ROWS, N_QKV, K_DIM);
    }

    // 2) fused tensor-core window attention (reg-P, single fill)
    {
        dim3 grid(NH_, NWIN_);
        win_attn_tc<<<grid, 256, AT_SMEM>>>(qkv_s, o_s);
    }

    // 3) proj GEMM -> final output
    {
        dim3 grid(N_PROJ / 128, M_ROWS / 128);
        gemm_tf32_mma<<<grid, 256, GEMM_SMEM>>>(o_s, wp, proj_b, out,
                                                M_ROWS, N_PROJ, K_DIM);
    }
}

// round 17
// speedup vs baseline: 1.1549x; 1.0110x over previous
#include <cuda_runtime.h>
#include <cuda_bf16.h>
#include <cstdint>

// ---------------------------------------------------------------------------
// Problem constants
// ---------------------------------------------------------------------------
#define B_       16
#define H_       56
#define W_       56
#define C_       768
#define WS_      14
#define NH_      12
#define HD_      64
#define NTOK_    196
#define NWIN_    256
#define M_ROWS   50176
#define K_DIM    768
#define N_QKV    2304
#define N_PROJ   768

// Scratch (device globals — allocation-free rule)
__device__ float g_qkv[(size_t)M_ROWS * N_QKV];
__device__ float g_o  [(size_t)M_ROWS * N_PROJ];
__device__ float g_xr [(size_t)M_ROWS * K_DIM];
__device__ float g_wq [(size_t)N_QKV  * K_DIM];
__device__ float g_wp [(size_t)N_PROJ * K_DIM];

// ---------------------------------------------------------------------------
// helpers
// ---------------------------------------------------------------------------
__device__ __forceinline__ float tf32_rna(float x) {
    uint32_t r;
    asm("cvt.rna.tf32.f32 %0, %1;" : "=r"(r) : "f"(x));
    return __uint_as_float(r);
}
__device__ __forceinline__ float4 rna4(float4 v) {
    v.x = tf32_rna(v.x); v.y = tf32_rna(v.y);
    v.z = tf32_rna(v.z); v.w = tf32_rna(v.w);
    return v;
}
__device__ __forceinline__ uint32_t smem_u32(const void* p) {
    uint32_t a;
    asm("{ .reg .u64 t; cvta.to.shared.u64 t, %1; cvt.u32.u64 %0, t; }" : "=r"(a) : "l"(p));
    return a;
}
__device__ __forceinline__ void cp_async16(uint32_t dst, const void* src) {
    asm volatile("cp.async.cg.shared.global [%0], [%1], 16;" :: "r"(dst), "l"(src) : "memory");
}
#define CP_COMMIT() asm volatile("cp.async.commit_group;" ::: "memory")
#define CP_WAIT(N)  asm volatile("cp.async.wait_group %0;" :: "n"(N) : "memory")

__device__ __forceinline__ void mma_m16n8k8(float d[4], const uint32_t a[4], const uint32_t b[2]) {
    asm volatile(
        "mma.sync.aligned.m16n8k8.row.col.f32.tf32.tf32.f32 "
        "{%0,%1,%2,%3}, {%4,%5,%6,%7}, {%8,%9}, {%0,%1,%2,%3};"
        : "+f"(d[0]), "+f"(d[1]), "+f"(d[2]), "+f"(d[3])
        : "r"(a[0]), "r"(a[1]), "r"(a[2]), "r"(a[3]), "r"(b[0]), "r"(b[1]));
}

// ---------------------------------------------------------------------------
// Merged tf32 rounding kernel: x, qkv_w, proj_w in ONE launch.
// ---------------------------------------------------------------------------
#define NX4 (M_ROWS * K_DIM / 4)
#define NQ4 (N_QKV  * K_DIM / 4)
#define NP4 (N_PROJ * K_DIM / 4)

__global__ void cvt_all_kernel(const float* __restrict__ x,  float* __restrict__ xr,
                               const float* __restrict__ wqi, float* __restrict__ wq,
                               const float* __restrict__ wpi, float* __restrict__ wp)
{
    int i = blockIdx.x * blockDim.x + threadIdx.x;
    if (i < NX4) { ((float4*)xr)[i] = rna4(((const float4*)x)[i]); return; }
    i -= NX4;
    if (i < NQ4) { ((float4*)wq)[i] = rna4(((const float4*)wqi)[i]); return; }
    i -= NQ4;
    if (i < NP4) ((float4*)wp)[i] = rna4(((const float4*)wpi)[i]);
}

// ---------------------------------------------------------------------------
// tf32 mma.sync GEMM (NT) — EXACT R6 text (measured best, 5 runs at 921-926us
// QKV): 128x128x32 tile, 8 warps (warp tile 64x32), 2-stage cp.async, one
// __syncthreads per k-tile, 2 CTAs/SM, LDS.64 frag loads via k-slot
// re-pairing (cols 2t,2t+1), ROWPAD=40 bank-conflict-free. DO NOT TOUCH.
// ---------------------------------------------------------------------------
#define BKG      32
#define STAGES   2
#define ROWPAD   40
#define TILE_B   (128 * ROWPAD * 4)            // 20480 B
#define GEMM_SMEM (2 * STAGES * TILE_B)        // 81920 B

__global__ __launch_bounds__(256, 2)
void gemm_tf32_mma(const float* __restrict__ A, const float* __restrict__ Bt,
                   const float* __restrict__ bias, float* __restrict__ C,
                   int M, int N, int K)
{
    extern __shared__ char sm[];
    float* smA = (float*)sm;
    float* smB = (float*)(sm + STAGES * TILE_B);

    const int tid  = threadIdx.x;
    const int wid  = tid >> 5;
    const int lane = tid & 31;
    const int g    = lane >> 2;
    const int t    = lane & 3;
    const int m0   = blockIdx.y * 128;
    const int n0   = blockIdx.x * 128;
    const int wm   = (wid & 1) * 64;
    const int wn   = (wid >> 1) * 32;
    const int ktiles = K / BKG;

    const uint32_t sbA = smem_u32(smA);
    const uint32_t sbB = smem_u32(smB);

    auto issue_tile = [&](int kt, int s) {
        const float* Ag = A  + (size_t)m0 * K + (size_t)kt * BKG;
        const float* Bg = Bt + (size_t)n0 * K + (size_t)kt * BKG;
        #pragma unroll
        for (int i = 0; i < 4; i++) {
            const int f   = tid + 256 * i;
            const int row = f >> 3;
            const int c4  = f & 7;
            const uint32_t so = (uint32_t)(s * TILE_B + (row * ROWPAD + c4 * 4) * 4);
            cp_async16(sbA + so, Ag + (size_t)row * K + c4 * 4);
            cp_async16(sbB + so, Bg + (size_t)row * K + c4 * 4);
        }
    };

    issue_tile(0, 0); CP_COMMIT();

    float acc[4][4][4];
    #pragma unroll
    for (int i = 0; i < 4; i++)
        #pragma unroll
        for (int j = 0; j < 4; j++)
            #pragma unroll
            for (int r = 0; r < 4; r++) acc[i][j][r] = 0.f;

    for (int kt = 0; kt < ktiles; kt++) {
        CP_WAIT(0);
        __syncthreads();
        if (kt + 1 < ktiles) {
            issue_tile(kt + 1, (kt + 1) & 1);
            CP_COMMIT();
        }

        const int s = kt & 1;
        const float* As = smA + s * (TILE_B / 4);
        const float* Bs = smB + s * (TILE_B / 4);

        #pragma unroll
        for (int kk = 0; kk < 4; kk++) {
            uint32_t a[4][4];
            #pragma unroll
            for (int fm = 0; fm < 4; fm++) {
                const int ra = wm + fm * 16 + g;
                const float2 lo = *(const float2*)&As[ra * ROWPAD + kk * 8 + 2 * t];
                const float2 hi = *(const float2*)&As[(ra + 8) * ROWPAD + kk * 8 + 2 * t];
                a[fm][0] = __float_as_uint(lo.x);
                a[fm][1] = __float_as_uint(hi.x);
                a[fm][2] = __float_as_uint(lo.y);
                a[fm][3] = __float_as_uint(hi.y);
            }
            uint32_t b[4][2];
            #pragma unroll
            for (int fn = 0; fn < 4; fn++) {
                const float2 v = *(const float2*)&Bs[(wn + fn * 8 + g) * ROWPAD + kk * 8 + 2 * t];
                b[fn][0] = __float_as_uint(v.x);
                b[fn][1] = __float_as_uint(v.y);
            }
            #pragma unroll
            for (int fm = 0; fm < 4; fm++)
                #pragma unroll
                for (int fn = 0; fn < 4; fn++)
                    mma_m16n8k8(acc[fm][fn], a[fm], b[fn]);
        }
    }
    __syncthreads();

    #pragma unroll
    for (int fm = 0; fm < 4; fm++) {
        const int r0 = m0 + wm + fm * 16 + g;
        #pragma unroll
        for (int fn = 0; fn < 4; fn++) {
            const int c = n0 + wn + fn * 8 + 2 * t;
            const float b0 = bias[c], b1 = bias[c + 1];
            float2 v0 = make_float2(acc[fm][fn][0] + b0, acc[fm][fn][1] + b1);
            float2 v1 = make_float2(acc[fm][fn][2] + b0, acc[fm][fn][3] + b1);
            *(float2*)(C + (size_t)r0 * N + c)       = v0;
            *(float2*)(C + (size_t)(r0 + 8) * N + c) = v1;
        }
    }
}

// ---------------------------------------------------------------------------
// Tensor-core fused window attention — R16 reg-P structure + NO-MAX softmax,
// BATCHED exp (R12 numerics, R16 scheduling):
//   after QK, exponentiate the whole sacc block in place (MUFU pipelines,
//   off the PV critical path), l = lane-local partial (each t-quad lane owns
//   disjoint keys 2t,2t+1), reduced once with 4 shfl in the epilogue.
// No row-max tree, no oacc rescale, no mrow/al chain, no per-chunk shfls.
// Masked tail keys: s=-1e30 -> exp=0.
// ---------------------------------------------------------------------------
#define KPAD 72
#define VPAD 68
#define AT_SMEM ((200 * KPAD + 200 * VPAD) * 4)   // 112000 B

__global__ __launch_bounds__(256, 1)
void win_attn_tc(const float* __restrict__ qkv, float* __restrict__ o)
{
    extern __shared__ float s[];
    float* Ks = s;                 // [200][KPAD]
    float* Vs = Ks + 200 * KPAD;   // [200][VPAD]

    const int head = blockIdx.x;
    const int win  = blockIdx.y;
    const int b  = win >> 4;
    const int hb = (win >> 2) & 3;
    const int wb = win & 3;

    const int tid  = threadIdx.x;
    const int w    = tid >> 5;
    const int lane = tid & 31;
    const int g    = lane >> 2;
    const int t    = lane & 3;

    // ---- K/V fill (rows 0..199; 196..199 zero), tf32-rounded ----
    for (int idx = tid; idx < 200 * 16; idx += 256) {
        const int n  = idx >> 4;
        const int d4 = (idx & 15) * 4;
        float4 kv = make_float4(0.f, 0.f, 0.f, 0.f);
        float4 vv = kv;
        if (n < NTOK_) {
            const int rr = n / WS_;
            const int cc = n - rr * WS_;
            const size_t row = (size_t)((b * H_ + hb * WS_ + rr) * W_ + (wb * WS_ + cc));
            const float* p = qkv + row * N_QKV + head * HD_ + d4;
            kv = rna4(*(const float4*)(p + C_));
            vv = rna4(*(const float4*)(p + 2 * C_));
        }
        *(float4*)&Ks[n * KPAD + d4] = kv;
        *(float4*)&Vs[n * VPAD + d4] = vv;
    }

    // ---- raster bases for this thread's 4 query rows ----
    int rb[2][2];
    #pragma unroll
    for (int mt = 0; mt < 2; mt++)
        #pragma unroll
        for (int hf = 0; hf < 2; hf++) {
            const int n = w * 32 + mt * 16 + g + hf * 8;
            if (n < NTOK_) {
                const int rr = n / WS_;
                const int cc = n - rr * WS_;
                rb[mt][hf] = (b * H_ + hb * WS_ + rr) * W_ + (wb * WS_ + cc);
            } else rb[mt][hf] = -1;
        }

    // ---- Q a-frags (slots = cols 2t,2t+1; pre-scaled, tf32-rounded) ----
    uint32_t q[2][8][4];
    #pragma unroll
    for (int mt = 0; mt < 2; mt++) {
        const float* p0 = (rb[mt][0] >= 0) ? qkv + (size_t)rb[mt][0] * N_QKV + head * HD_ : nullptr;
        const float* p1 = (rb[mt][1] >= 0) ? qkv + (size_t)rb[mt][1] * N_QKV + head * HD_ : nullptr;
        #pragma unroll
        for (int kk = 0; kk < 8; kk++) {
            float2 lo = p0 ? *(const float2*)(p0 + kk * 8 + 2 * t) : make_float2(0.f, 0.f);
            float2 hi = p1 ? *(const float2*)(p1 + kk * 8 + 2 * t) : make_float2(0.f, 0.f);
            q[mt][kk][0] = __float_as_uint(tf32_rna(lo.x * 0.125f));
            q[mt][kk][1] = __float_as_uint(tf32_rna(hi.x * 0.125f));
            q[mt][kk][2] = __float_as_uint(tf32_rna(lo.y * 0.125f));
            q[mt][kk][3] = __float_as_uint(tf32_rna(hi.y * 0.125f));
        }
    }
    __syncthreads();

    if (w == 7) return;                     // rows 224..255 all padding

    float oacc[2][8][4];
    #pragma unroll
    for (int mt = 0; mt < 2; mt++)
        #pragma unroll
        for (int nt = 0; nt < 8; nt++)
            #pragma unroll
            for (int r = 0; r < 4; r++) oacc[mt][nt][r] = 0.f;

    float lrow[2][2] = {{0.f, 0.f}, {0.f, 0.f}};   // lane-local partials

    // ---- 3 full chunks of 64 keys ----
    for (int c = 0; c < 3; c++) {
        const int n0c = c * 64;

        float sacc[2][8][4];
        #pragma unroll
        for (int mt = 0; mt < 2; mt++)
            #pragma unroll
            for (int nt = 0; nt < 8; nt++)
                #pragma unroll
                for (int r = 0; r < 4; r++) sacc[mt][nt][r] = 0.f;

        #pragma unroll
        for (int kk = 0; kk < 8; kk++) {
            #pragma unroll
            for (int nt = 0; nt < 8; nt++) {
                const float2 kv = *(const float2*)&Ks[(n0c + nt * 8 + g) * KPAD + kk * 8 + 2 * t];
                uint32_t bfr[2];
                bfr[0] = __float_as_uint(kv.x);
                bfr[1] = __float_as_uint(kv.y);
                mma_m16n8k8(sacc[0][nt], q[0][kk], bfr);
                mma_m16n8k8(sacc[1][nt], q[1][kk], bfr);
            }
        }

        // batched no-max exp: sacc <- tf32_rna(exp(sacc)); l partials accumulate
        #pragma unroll
        for (int mt = 0; mt < 2; mt++) {
            #pragma unroll
            for (int nt = 0; nt < 8; nt++) {
                const float p0 = __expf(sacc[mt][nt][0]);
                const float p1 = __expf(sacc[mt][nt][1]);
                const float p2 = __expf(sacc[mt][nt][2]);
                const float p3 = __expf(sacc[mt][nt][3]);
                lrow[mt][0] += p0 + p1;
                lrow[mt][1] += p2 + p3;
                sacc[mt][nt][0] = tf32_rna(p0);
                sacc[mt][nt][1] = tf32_rna(p1);
                sacc[mt][nt][2] = tf32_rna(p2);
                sacc[mt][nt][3] = tf32_rna(p3);
            }
        }

        // PV: a-frag = register P (slots = keys 2t,2t+1), b = V rows (2t,2t+1)
        #pragma unroll
        for (int kk2 = 0; kk2 < 8; kk2++) {
            uint32_t a0[4], a1[4];
            a0[0] = __float_as_uint(sacc[0][kk2][0]);
            a0[1] = __float_as_uint(sacc[0][kk2][2]);
            a0[2] = __float_as_uint(sacc[0][kk2][1]);
            a0[3] = __float_as_uint(sacc[0][kk2][3]);
            a1[0] = __float_as_uint(sacc[1][kk2][0]);
            a1[1] = __float_as_uint(sacc[1][kk2][2]);
            a1[2] = __float_as_uint(sacc[1][kk2][1]);
            a1[3] = __float_as_uint(sacc[1][kk2][3]);
            const float* v0p = Vs + (n0c + kk2 * 8 + 2 * t) * VPAD;
            #pragma unroll
            for (int ntd = 0; ntd < 8; ntd++) {
                uint32_t bfr[2];
                bfr[0] = __float_as_uint(v0p[ntd * 8 + g]);
                bfr[1] = __float_as_uint(v0p[VPAD + ntd * 8 + g]);
                mma_m16n8k8(oacc[0][ntd], a0, bfr);
                mma_m16n8k8(oacc[1][ntd], a1, bfr);
            }
        }
    }

    // ---- tail chunk: keys 192..199 (4 valid) ----
    {
        float st[2][4] = {{0.f, 0.f, 0.f, 0.f}, {0.f, 0.f, 0.f, 0.f}};
        #pragma unroll
        for (int kk = 0; kk < 8; kk++) {
            const float2 kv = *(const float2*)&Ks[(192 + g) * KPAD + kk * 8 + 2 * t];
            uint32_t bfr[2];
            bfr[0] = __float_as_uint(kv.x);
            bfr[1] = __float_as_uint(kv.y);
            mma_m16n8k8(st[0], q[0][kk], bfr);
            mma_m16n8k8(st[1], q[1][kk], bfr);
        }
        const int j0 = 192 + 2 * t;
        uint32_t a0[4], a1[4];
        #pragma unroll
        for (int mt = 0; mt < 2; mt++) {
            if (j0 >= NTOK_)     { st[mt][0] = -1e30f; st[mt][2] = -1e30f; }
            if (j0 + 1 >= NTOK_) { st[mt][1] = -1e30f; st[mt][3] = -1e30f; }
            const float p0 = __expf(st[mt][0]);
            const float p1 = __expf(st[mt][1]);
            const float p2 = __expf(st[mt][2]);
            const float p3 = __expf(st[mt][3]);
            lrow[mt][0] += p0 + p1;
            lrow[mt][1] += p2 + p3;
            uint32_t* aa = (mt == 0) ? a0 : a1;
            aa[0] = __float_as_uint(tf32_rna(p0));
            aa[1] = __float_as_uint(tf32_rna(p2));
            aa[2] = __float_as_uint(tf32_rna(p1));
            aa[3] = __float_as_uint(tf32_rna(p3));
        }
        const float* v0p = Vs + (192 + 2 * t) * VPAD;
        #pragma unroll
        for (int ntd = 0; ntd < 8; ntd++) {
            uint32_t bfr[2];
            bfr[0] = __float_as_uint(v0p[ntd * 8 + g]);
            bfr[1] = __float_as_uint(v0p[VPAD + ntd * 8 + g]);
            mma_m16n8k8(oacc[0][ntd], a0, bfr);
            mma_m16n8k8(oacc[1][ntd], a1, bfr);
        }
    }

    // ---- epilogue: reduce l across the t-quad, divide, write ----
    #pragma unroll
    for (int mt = 0; mt < 2; mt++) {
        #pragma unroll
        for (int hf = 0; hf < 2; hf++) {
            float l = lrow[mt][hf];
            l += __shfl_xor_sync(0xffffffffu, l, 1);
            l += __shfl_xor_sync(0xffffffffu, l, 2);
            lrow[mt][hf] = l;
        }
    }
    #pragma unroll
    for (int mt = 0; mt < 2; mt++) {
        const float i0 = 1.f / lrow[mt][0];
        const float i1 = 1.f / lrow[mt][1];
        if (rb[mt][0] >= 0) {
            float* op = o + (size_t)rb[mt][0] * N_PROJ + head * HD_;
            #pragma unroll
            for (int ntd = 0; ntd < 8; ntd++)
                *(float2*)&op[ntd * 8 + 2 * t] =
                    make_float2(tf32_rna(oacc[mt][ntd][0] * i0), tf32_rna(oacc[mt][ntd][1] * i0));
        }
        if (rb[mt][1] >= 0) {
            float* op = o + (size_t)rb[mt][1] * N_PROJ + head * HD_;
            #pragma unroll
            for (int ntd = 0; ntd < 8; ntd++)
                *(float2*)&op[ntd * 8 + 2 * t] =
                    make_float2(tf32_rna(oacc[mt][ntd][2] * i1), tf32_rna(oacc[mt][ntd][3] * i1));
        }
    }
}

// ---------------------------------------------------------------------------
extern "C" void kernel_launch(void* const* d_in, const int* in_sizes, int n_in,
                              void* d_out, int out_size)
{
    const float* x      = (const float*)d_in[0];
    const float* qkv_w  = (const float*)d_in[1];
    const float* qkv_b  = (const float*)d_in[2];
    const float* proj_w = (const float*)d_in[3];
    const float* proj_b = (const float*)d_in[4];
    float* out = (float*)d_out;

    float *qkv_s, *o_s, *xr, *wq, *wp;
    cudaGetSymbolAddress((void**)&qkv_s, g_qkv);
    cudaGetSymbolAddress((void**)&o_s,   g_o);
    cudaGetSymbolAddress((void**)&xr,    g_xr);
    cudaGetSymbolAddress((void**)&wq,    g_wq);
    cudaGetSymbolAddress((void**)&wp,    g_wp);

    cudaFuncSetAttribute(gemm_tf32_mma,
                         cudaFuncAttributeMaxDynamicSharedMemorySize, GEMM_SMEM);
    cudaFuncSetAttribute(win_attn_tc,
                         cudaFuncAttributeMaxDynamicSharedMemorySize, AT_SMEM);

    // 0) tf32-round all GEMM inputs in ONE launch
    {
        const int ntot = NX4 + NQ4 + NP4;
        cvt_all_kernel<<<(ntot + 255) / 256, 256>>>(x, xr, qkv_w, wq, proj_w, wp);
    }

    // 1) QKV GEMM
    {
        dim3 grid(N_QKV / 128, M_ROWS / 128);
        gemm_tf32_mma<<<grid, 256, GEMM_SMEM>>>(xr, wq, qkv_b, qkv_s,
                                                M_ROWS, N_QKV, K_DIM);
    }

    // 2) fused tensor-core window attention (reg-P, no-max batched softmax)
    {
        dim3 grid(NH_, NWIN_);
        win_attn_tc<<<grid, 256, AT_SMEM>>>(qkv_s, o_s);
    }

    // 3) proj GEMM -> final output
    {
        dim3 grid(N_PROJ / 128, M_ROWS / 128);
        gemm_tf32_mma<<<grid, 256, GEMM_SMEM>>>(o_s, wp, proj_b, out,
                                                M_ROWS, N_PROJ, K_DIM);
    }
}